// round 2
// baseline (speedup 1.0000x reference)
#include <cuda_runtime.h>

// H_13048110646034: butterfly-permuted complex locally-connected layer.
// B=8, N=16384, R=16, P=4096, T=64.
// One warp per block p. Lane = (bh, og): og = lane&15 -> output quad (4 floats),
// bh = lane>>4 -> batch half (b = bh*4 + 0..3). Each weight quad is loaded once
// per warp (2 cache lines per LDG.128 after intra-warp dedup) and reused for
// 4 batches x (re+im) = 16 FMAs -> weight bytes traverse L1 exactly once.

#define B_  8
#define N_  16384
#define P_  4096
#define T_  64

__global__ __launch_bounds__(128, 6)
void butterfly_local_v2(const float* __restrict__ x,
                        const float* __restrict__ Wrr,
                        const float* __restrict__ Wri,
                        const float* __restrict__ Wir,
                        const float* __restrict__ Wii,
                        const int*   __restrict__ perm,
                        float* __restrict__ out)
{
    const int w    = threadIdx.x >> 5;      // warp in CTA: 0..3
    const int lane = threadIdx.x & 31;
    const int p    = blockIdx.x * 4 + w;    // one p per warp

    __shared__ float xs[4][2][B_][T_];      // [warp][c][b][i]  16 KB

    // ---- gather: 1024 floats (= 256 float4) for this warp's p ----
    #pragma unroll
    for (int it = 0; it < 8; it++) {
        const int u   = it * 32 + lane;     // 0..255
        const int f4  = u & 3;
        const int row = u >> 2;             // 0..63
        const int j   = row & 3;
        const int cb  = row >> 2;           // 0..15
        const int b   = cb >> 1;
        const int c   = cb & 1;
        const int n   = __ldg(&perm[p * 4 + j]);
        const float4 v = *(const float4*)&x[(((size_t)(b * 2 + c) * N_) + n) * 16 + f4 * 4];
        *(float4*)&xs[w][c][b][j * 16 + f4 * 4] = v;
    }
    __syncwarp();

    const int og = lane & 15;               // output quad 0..15
    const int bh = lane >> 4;               // batch half 0..1

    const size_t wq = (size_t)p * 1024 + og;    // float4 index into W[p]
    const float4* __restrict__ wrr = (const float4*)Wrr + wq;
    const float4* __restrict__ wri = (const float4*)Wri + wq;
    const float4* __restrict__ wir = (const float4*)Wir + wq;
    const float4* __restrict__ wii = (const float4*)Wii + wq;

    float4 aR[4], aI[4];
    #pragma unroll
    for (int k = 0; k < 4; k++) {
        aR[k] = make_float4(0.f, 0.f, 0.f, 0.f);
        aI[k] = make_float4(0.f, 0.f, 0.f, 0.f);
    }

    #pragma unroll 4
    for (int i = 0; i < T_; i++) {
        const float4 wa = wrr[i * 16];
        const float4 wb = wri[i * 16];
        const float4 wc = wir[i * 16];
        const float4 wd = wii[i * 16];
        #pragma unroll
        for (int k = 0; k < 4; k++) {
            const int   b  = bh * 4 + k;
            const float xr = xs[w][0][b][i];
            const float xi = xs[w][1][b][i];
            aR[k].x = fmaf(xr, wa.x, aR[k].x); aR[k].x = fmaf(xi, wb.x, aR[k].x);
            aR[k].y = fmaf(xr, wa.y, aR[k].y); aR[k].y = fmaf(xi, wb.y, aR[k].y);
            aR[k].z = fmaf(xr, wa.z, aR[k].z); aR[k].z = fmaf(xi, wb.z, aR[k].z);
            aR[k].w = fmaf(xr, wa.w, aR[k].w); aR[k].w = fmaf(xi, wb.w, aR[k].w);
            aI[k].x = fmaf(xr, wc.x, aI[k].x); aI[k].x = fmaf(xi, wd.x, aI[k].x);
            aI[k].y = fmaf(xr, wc.y, aI[k].y); aI[k].y = fmaf(xi, wd.y, aI[k].y);
            aI[k].z = fmaf(xr, wc.z, aI[k].z); aI[k].z = fmaf(xi, wd.z, aI[k].z);
            aI[k].w = fmaf(xr, wc.w, aI[k].w); aI[k].w = fmaf(xi, wd.w, aI[k].w);
        }
    }

    // ---- store: out[b, c, 4p..4p+3, :] is a contiguous 64-float run ----
    #pragma unroll
    for (int k = 0; k < 4; k++) {
        const int b = bh * 4 + k;
        const size_t reOff = (((size_t)(b * 2 + 0) * N_) + 4 * (size_t)p) * 16 + og * 4;
        const size_t imOff = (((size_t)(b * 2 + 1) * N_) + 4 * (size_t)p) * 16 + og * 4;
        *(float4*)&out[reOff] = aR[k];
        *(float4*)&out[imOff] = aI[k];
    }
}

extern "C" void kernel_launch(void* const* d_in, const int* in_sizes, int n_in,
                              void* d_out, int out_size)
{
    const float* x    = (const float*)d_in[0];
    const float* Wrr  = (const float*)d_in[1];
    const float* Wri  = (const float*)d_in[2];
    const float* Wir  = (const float*)d_in[3];
    const float* Wii  = (const float*)d_in[4];
    const int*   perm = (const int*)d_in[5];
    float* out = (float*)d_out;

    butterfly_local_v2<<<P_ / 4, 128>>>(x, Wrr, Wri, Wir, Wii, perm, out);
}

// round 3
// speedup vs baseline: 1.6532x; 1.6532x over previous
#include <cuda_runtime.h>

// H_13048110646034: butterfly-permuted complex locally-connected layer.
// B=8, N=16384, R=16, P=4096, T=64.
// v3: cp.async weight streaming into smem (2-stage ring, 4 chunks of 16 i-rows),
// compute from smem with warp-level 8-way broadcast of weight quads.
// Thread (tid 0..255): warp w = tid>>5, cout = w&1 (re/im), oggrp = w>>1;
// lane: b = lane>>2, ogsub = lane&3, og = oggrp*4+ogsub.
// Each thread accumulates ONE output quad: out[b, cout, 4p + og/4, (og%4)*4..+3].

#define B_   8
#define N_   16384
#define P_   4096
#define T_   64
#define XSTR 68   // padded x row stride (floats): conflict-free b-stride

__device__ __forceinline__ void cp_async16(void* smem_dst, const void* gsrc) {
    unsigned saddr = (unsigned)__cvta_generic_to_shared(smem_dst);
    asm volatile("cp.async.cg.shared.global [%0], [%1], 16;\n" :: "r"(saddr), "l"(gsrc));
}
__device__ __forceinline__ void cp_commit() {
    asm volatile("cp.async.commit_group;\n");
}
template <int N>
__device__ __forceinline__ void cp_wait() {
    asm volatile("cp.async.wait_group %0;\n" :: "n"(N));
}

__global__ __launch_bounds__(256, 6)
void butterfly_local_v3(const float* __restrict__ x,
                        const float* __restrict__ Wrr,
                        const float* __restrict__ Wri,
                        const float* __restrict__ Wir,
                        const float* __restrict__ Wii,
                        const int*   __restrict__ perm,
                        float* __restrict__ out)
{
    const int p   = blockIdx.x;
    const int tid = threadIdx.x;

    // Wsm[buf][mat][i_local][o] : 2 * 4 * 16 * 64 floats = 32 KB
    __shared__ float Wsm[2][4][16][64];
    // xs[c][b][i] with padded stride
    __shared__ float xs[2][B_][XSTR];

    const float* __restrict__ Wmat[4] = { Wrr, Wri, Wir, Wii };

    // ---- issue chunk 0 and 1 (each: 16 i-rows of all 4 mats, 16 KB) ----
    // per chunk per thread: one float4 per mat.
    {
        const size_t base = (size_t)p * 1024 + tid;   // float4 units
        #pragma unroll
        for (int m = 0; m < 4; m++)
            cp_async16(&Wsm[0][m][0][0] + tid * 4, (const float4*)Wmat[m] + base);
        cp_commit();
        #pragma unroll
        for (int m = 0; m < 4; m++)
            cp_async16(&Wsm[1][m][0][0] + tid * 4, (const float4*)Wmat[m] + base + 256);
        cp_commit();
    }

    // ---- x gather: 256 float4 = 1024 floats, 1 float4 per thread ----
    {
        const int f4  = tid & 3;
        const int row = tid >> 2;            // 0..63
        const int j   = row & 3;
        const int cb  = row >> 2;            // 0..15
        const int gb  = cb >> 1;
        const int gc  = cb & 1;
        const int n   = __ldg(&perm[p * 4 + j]);
        const float4 v = *(const float4*)&x[(((size_t)(gb * 2 + gc) * N_) + n) * 16 + f4 * 4];
        float* dst = &xs[gc][gb][j * 16 + f4 * 4];
        dst[0] = v.x; dst[1] = v.y; dst[2] = v.z; dst[3] = v.w;
    }

    const int w     = tid >> 5;
    const int cout  = w & 1;                 // 0 = re, 1 = im
    const int oggrp = w >> 1;                // 0..3
    const int lane  = tid & 31;
    const int b     = lane >> 2;             // 0..7
    const int og    = oggrp * 4 + (lane & 3);// 0..15

    const int matA = cout * 2;               // rr or ir
    const int matB = cout * 2 + 1;           // ri or ii

    float4 acc = make_float4(0.f, 0.f, 0.f, 0.f);

    #define COMPUTE_CHUNK(BUF, CBASE)                                         \
        _Pragma("unroll")                                                     \
        for (int ii = 0; ii < 16; ii++) {                                     \
            const int i = (CBASE) * 16 + ii;                                  \
            const float xr = xs[0][b][i];                                     \
            const float xi = xs[1][b][i];                                     \
            const float4 wa = *(const float4*)&Wsm[BUF][matA][ii][og * 4];    \
            const float4 wb = *(const float4*)&Wsm[BUF][matB][ii][og * 4];    \
            acc.x = fmaf(xr, wa.x, acc.x); acc.x = fmaf(xi, wb.x, acc.x);     \
            acc.y = fmaf(xr, wa.y, acc.y); acc.y = fmaf(xi, wb.y, acc.y);     \
            acc.z = fmaf(xr, wa.z, acc.z); acc.z = fmaf(xi, wb.z, acc.z);     \
            acc.w = fmaf(xr, wa.w, acc.w); acc.w = fmaf(xi, wb.w, acc.w);     \
        }

    // ---- chunk 0 (buf0) ----
    cp_wait<1>();
    __syncthreads();                          // also covers x gather STS
    COMPUTE_CHUNK(0, 0);
    __syncthreads();                          // all done reading buf0

    // issue chunk 2 -> buf0
    {
        const size_t base = (size_t)p * 1024 + tid + 512;
        #pragma unroll
        for (int m = 0; m < 4; m++)
            cp_async16(&Wsm[0][m][0][0] + tid * 4, (const float4*)Wmat[m] + base);
        cp_commit();
    }

    // ---- chunk 1 (buf1) ----
    cp_wait<1>();
    __syncthreads();
    COMPUTE_CHUNK(1, 1);
    __syncthreads();

    // issue chunk 3 -> buf1
    {
        const size_t base = (size_t)p * 1024 + tid + 768;
        #pragma unroll
        for (int m = 0; m < 4; m++)
            cp_async16(&Wsm[1][m][0][0] + tid * 4, (const float4*)Wmat[m] + base);
        cp_commit();
    }

    // ---- chunk 2 (buf0) ----
    cp_wait<1>();
    __syncthreads();
    COMPUTE_CHUNK(0, 2);

    // ---- chunk 3 (buf1) ----
    cp_wait<0>();
    __syncthreads();
    COMPUTE_CHUNK(1, 3);

    // ---- store: out[b, cout, 4p + og/4, :] quad at og*4 ----
    const size_t off = (((size_t)(b * 2 + cout) * N_) + 4 * (size_t)p) * 16 + og * 4;
    *(float4*)&out[off] = acc;
}

extern "C" void kernel_launch(void* const* d_in, const int* in_sizes, int n_in,
                              void* d_out, int out_size)
{
    const float* x    = (const float*)d_in[0];
    const float* Wrr  = (const float*)d_in[1];
    const float* Wri  = (const float*)d_in[2];
    const float* Wir  = (const float*)d_in[3];
    const float* Wii  = (const float*)d_in[4];
    const int*   perm = (const int*)d_in[5];
    float* out = (float*)d_out;

    butterfly_local_v3<<<P_, 256>>>(x, Wrr, Wri, Wir, Wii, perm, out);
}

// round 4
// speedup vs baseline: 2.2396x; 1.3547x over previous
#include <cuda_runtime.h>

// H_13048110646034 v4: one warp per block p; weights streamed via cp.async
// (2-stage ring, 8 chunks of 8 i-rows); lane = (oslot, bslot, cout) owns
// 8 o-floats x 4 batches -> weight lane-side smem traffic only 2x unique bytes
// (vs 8x in v3), dropping the L1/LDS return-path load below the DRAM floor.

#define B_  8
#define N_  16384
#define P_  4096

__device__ __forceinline__ void cp_async16(void* smem_dst, const void* gsrc) {
    unsigned saddr = (unsigned)__cvta_generic_to_shared(smem_dst);
    asm volatile("cp.async.cg.shared.global [%0], [%1], 16;\n" :: "r"(saddr), "l"(gsrc));
}
__device__ __forceinline__ void cp_commit() { asm volatile("cp.async.commit_group;\n"); }
template <int N>
__device__ __forceinline__ void cp_wait() {
    asm volatile("cp.async.wait_group %0;\n" :: "n"(N));
}

__global__ __launch_bounds__(64, 8)
void butterfly_local_v4(const float* __restrict__ x,
                        const float* __restrict__ Wrr,
                        const float* __restrict__ Wri,
                        const float* __restrict__ Wir,
                        const float* __restrict__ Wii,
                        const int*   __restrict__ perm,
                        float* __restrict__ out)
{
    const int w    = threadIdx.x >> 5;       // warp 0..1, one p each
    const int lane = threadIdx.x & 31;
    const int p    = blockIdx.x * 2 + w;

    // Weights: [warp][buf][mat][i_local 8][o 64]  = 32 KB
    __shared__ float Wsm[2][2][4][8][64];
    // x: [warp][i 64][b*2+c 16]                   = 8 KB
    __shared__ float xsm[2][64][16];

    const float* const Wm[4] = { Wrr, Wri, Wir, Wii };
    const size_t pq = (size_t)p * 1024;      // float4 units per mat per p

    // ---- fill helper: chunk c (i in [c*8, c*8+8)) of all 4 mats -> buf ----
    #define FILL_CHUNK(CC, BUF)                                               \
        {                                                                     \
            const int _c = (CC);                                              \
            _Pragma("unroll")                                                 \
            for (int k = 0; k < 16; k++) {                                    \
                const int mat = k >> 2;                                       \
                const int rem = (k & 3) * 32 + lane;                          \
                cp_async16(((float4*)&Wsm[w][BUF][mat][0][0]) + rem,          \
                           ((const float4*)Wm[mat]) + pq + _c * 128 + rem);   \
            }                                                                 \
            cp_commit();                                                      \
        }

    FILL_CHUNK(0, 0);
    FILL_CHUNK(1, 1);

    // ---- x gather: 1024 floats for this warp's p, stored as [i][b*2+c] ----
    #pragma unroll
    for (int it = 0; it < 8; it++) {
        const int u   = it * 32 + lane;      // 0..255
        const int f4  = u & 3;               // quad within 16-float row
        const int row = u >> 2;              // 0..63
        const int j   = row & 3;             // perm slot
        const int cb  = row >> 2;            // b*2 + c, 0..15
        const int b   = cb >> 1;
        const int c   = cb & 1;
        const int n   = __ldg(&perm[p * 4 + j]);
        const float4 v = *(const float4*)&x[(((size_t)cb * N_) + n) * 16 + f4 * 4];
        const int i0 = j * 16 + f4 * 4;
        xsm[w][i0 + 0][b * 2 + c] = v.x;
        xsm[w][i0 + 1][b * 2 + c] = v.y;
        xsm[w][i0 + 2][b * 2 + c] = v.z;
        xsm[w][i0 + 3][b * 2 + c] = v.w;
    }
    __syncwarp();

    const int oslot = lane & 7;              // o-quads oslot and oslot+8
    const int bslot = (lane >> 3) & 1;       // b = bslot*4 + 0..3
    const int cout  = lane >> 4;             // 0 = re, 1 = im
    const int matA  = cout * 2;
    const int matB  = cout * 2 + 1;

    float4 accLo[4], accHi[4];
    #pragma unroll
    for (int k = 0; k < 4; k++) {
        accLo[k] = make_float4(0.f, 0.f, 0.f, 0.f);
        accHi[k] = make_float4(0.f, 0.f, 0.f, 0.f);
    }

    for (int c = 0; c < 8; c++) {
        cp_wait<1>();
        __syncwarp();
        const int buf = c & 1;

        #pragma unroll
        for (int ii = 0; ii < 8; ii++) {
            const int i = c * 8 + ii;
            const float4 xa  = *(const float4*)&xsm[w][i][bslot * 8];
            const float4 xb  = *(const float4*)&xsm[w][i][bslot * 8 + 4];
            const float4 wA0 = *(const float4*)&Wsm[w][buf][matA][ii][oslot * 4];
            const float4 wA1 = *(const float4*)&Wsm[w][buf][matA][ii][32 + oslot * 4];
            const float4 wB0 = *(const float4*)&Wsm[w][buf][matB][ii][oslot * 4];
            const float4 wB1 = *(const float4*)&Wsm[w][buf][matB][ii][32 + oslot * 4];

            const float xr[4] = { xa.x, xa.z, xb.x, xb.z };
            const float xi[4] = { xa.y, xa.w, xb.y, xb.w };

            #pragma unroll
            for (int k = 0; k < 4; k++) {
                accLo[k].x = fmaf(xr[k], wA0.x, accLo[k].x); accLo[k].x = fmaf(xi[k], wB0.x, accLo[k].x);
                accLo[k].y = fmaf(xr[k], wA0.y, accLo[k].y); accLo[k].y = fmaf(xi[k], wB0.y, accLo[k].y);
                accLo[k].z = fmaf(xr[k], wA0.z, accLo[k].z); accLo[k].z = fmaf(xi[k], wB0.z, accLo[k].z);
                accLo[k].w = fmaf(xr[k], wA0.w, accLo[k].w); accLo[k].w = fmaf(xi[k], wB0.w, accLo[k].w);
                accHi[k].x = fmaf(xr[k], wA1.x, accHi[k].x); accHi[k].x = fmaf(xi[k], wB1.x, accHi[k].x);
                accHi[k].y = fmaf(xr[k], wA1.y, accHi[k].y); accHi[k].y = fmaf(xi[k], wB1.y, accHi[k].y);
                accHi[k].z = fmaf(xr[k], wA1.z, accHi[k].z); accHi[k].z = fmaf(xi[k], wB1.z, accHi[k].z);
                accHi[k].w = fmaf(xr[k], wA1.w, accHi[k].w); accHi[k].w = fmaf(xi[k], wB1.w, accHi[k].w);
            }
        }

        __syncwarp();                        // all lanes done reading buf
        if (c < 6) {
            FILL_CHUNK(c + 2, buf);
        } else {
            cp_commit();                     // keep group accounting uniform
        }
    }

    // ---- store: out[b, cout, 4p..4p+3, :] = contiguous 64-float run ----
    #pragma unroll
    for (int k = 0; k < 4; k++) {
        const int b = bslot * 4 + k;
        const size_t off = (((size_t)(b * 2 + cout) * N_) + 4 * (size_t)p) * 16;
        *(float4*)&out[off + oslot * 4]      = accLo[k];
        *(float4*)&out[off + 32 + oslot * 4] = accHi[k];
    }
    #undef FILL_CHUNK
}

extern "C" void kernel_launch(void* const* d_in, const int* in_sizes, int n_in,
                              void* d_out, int out_size)
{
    const float* x    = (const float*)d_in[0];
    const float* Wrr  = (const float*)d_in[1];
    const float* Wri  = (const float*)d_in[2];
    const float* Wir  = (const float*)d_in[3];
    const float* Wii  = (const float*)d_in[4];
    const int*   perm = (const int*)d_in[5];
    float* out = (float*)d_out;

    butterfly_local_v4<<<P_ / 2, 64>>>(x, Wrr, Wri, Wir, Wii, perm, out);
}

// round 5
// speedup vs baseline: 2.3975x; 1.0705x over previous
#include <cuda_runtime.h>

// H_13048110646034 v5: one warp per block p; cp.async weight ring with
// 4-i-row chunks (8 KB/warp ring vs 16 KB in v4) -> 9 CTAs/SM (18 warps)
// instead of 5 (10 warps), to densify DRAM request stream.
// Gather remapped (cb = lane&15) to kill the 16-way STS bank conflicts.

#define B_  8
#define N_  16384
#define P_  4096

__device__ __forceinline__ void cp_async16(void* smem_dst, const void* gsrc) {
    unsigned saddr = (unsigned)__cvta_generic_to_shared(smem_dst);
    asm volatile("cp.async.cg.shared.global [%0], [%1], 16;\n" :: "r"(saddr), "l"(gsrc));
}
__device__ __forceinline__ void cp_commit() { asm volatile("cp.async.commit_group;\n"); }
template <int N>
__device__ __forceinline__ void cp_wait() {
    asm volatile("cp.async.wait_group %0;\n" :: "n"(N));
}

__global__ __launch_bounds__(64, 9)
void butterfly_local_v5(const float* __restrict__ x,
                        const float* __restrict__ Wrr,
                        const float* __restrict__ Wri,
                        const float* __restrict__ Wir,
                        const float* __restrict__ Wii,
                        const int*   __restrict__ perm,
                        float* __restrict__ out)
{
    const int w    = threadIdx.x >> 5;       // warp 0..1, one p each
    const int lane = threadIdx.x & 31;
    const int p    = blockIdx.x * 2 + w;

    // Weights: [warp][buf][mat][i_local 4][o 64] = 16 KB total (8 KB/warp)
    __shared__ float Wsm[2][2][4][4][64];
    // x: [warp][i 64][cb 16] = 8 KB ; reads are aligned float4, broadcast
    __shared__ float xsm[2][64][16];

    const float* const Wm[4] = { Wrr, Wri, Wir, Wii };
    const size_t pq = (size_t)p * 1024;      // float4 units per mat per p

    // chunk CC covers i in [CC*4, CC*4+4): 64 float4 per mat -> 2 per lane
    #define FILL_CHUNK(CC, BUF)                                               \
        {                                                                     \
            const int _c = (CC);                                              \
            _Pragma("unroll")                                                 \
            for (int k = 0; k < 8; k++) {                                     \
                const int mat = k >> 1;                                       \
                const int rem = (k & 1) * 32 + lane;                          \
                cp_async16(((float4*)&Wsm[w][BUF][mat][0][0]) + rem,          \
                           ((const float4*)Wm[mat]) + pq + _c * 64 + rem);    \
            }                                                                 \
            cp_commit();                                                      \
        }

    FILL_CHUNK(0, 0);
    FILL_CHUNK(1, 1);

    // ---- x gather: lane carries cb = lane&15 so transposed STS spread banks.
    // 256 float4 loads: it 0..7, hi = lane>>4 -> (j, f4) = decode(it*2+hi).
    {
        const int cb = lane & 15;
        const int hi = lane >> 4;
        #pragma unroll
        for (int it = 0; it < 8; it++) {
            const int jf = it * 2 + hi;      // 0..15
            const int j  = jf >> 2;
            const int f4 = jf & 3;
            const int n  = __ldg(&perm[p * 4 + j]);
            const float4 v = *(const float4*)&x[(((size_t)cb * N_) + n) * 16 + f4 * 4];
            const int i0 = j * 16 + f4 * 4;
            xsm[w][i0 + 0][cb] = v.x;
            xsm[w][i0 + 1][cb] = v.y;
            xsm[w][i0 + 2][cb] = v.z;
            xsm[w][i0 + 3][cb] = v.w;
        }
    }
    __syncwarp();

    const int oslot = lane & 7;              // o-quads oslot and oslot+8
    const int bslot = (lane >> 3) & 1;       // b = bslot*4 + 0..3
    const int cout  = lane >> 4;             // 0 = re, 1 = im
    const int matA  = cout * 2;
    const int matB  = cout * 2 + 1;

    float4 accLo[4], accHi[4];
    #pragma unroll
    for (int k = 0; k < 4; k++) {
        accLo[k] = make_float4(0.f, 0.f, 0.f, 0.f);
        accHi[k] = make_float4(0.f, 0.f, 0.f, 0.f);
    }

    for (int c = 0; c < 16; c++) {
        cp_wait<1>();
        __syncwarp();
        const int buf = c & 1;

        #pragma unroll
        for (int ii = 0; ii < 4; ii++) {
            const int i = c * 4 + ii;
            const float4 xa  = *(const float4*)&xsm[w][i][bslot * 8];
            const float4 xb  = *(const float4*)&xsm[w][i][bslot * 8 + 4];
            const float4 wA0 = *(const float4*)&Wsm[w][buf][matA][ii][oslot * 4];
            const float4 wA1 = *(const float4*)&Wsm[w][buf][matA][ii][32 + oslot * 4];
            const float4 wB0 = *(const float4*)&Wsm[w][buf][matB][ii][oslot * 4];
            const float4 wB1 = *(const float4*)&Wsm[w][buf][matB][ii][32 + oslot * 4];

            const float xr[4] = { xa.x, xa.z, xb.x, xb.z };
            const float xi[4] = { xa.y, xa.w, xb.y, xb.w };

            #pragma unroll
            for (int k = 0; k < 4; k++) {
                accLo[k].x = fmaf(xr[k], wA0.x, accLo[k].x); accLo[k].x = fmaf(xi[k], wB0.x, accLo[k].x);
                accLo[k].y = fmaf(xr[k], wA0.y, accLo[k].y); accLo[k].y = fmaf(xi[k], wB0.y, accLo[k].y);
                accLo[k].z = fmaf(xr[k], wA0.z, accLo[k].z); accLo[k].z = fmaf(xi[k], wB0.z, accLo[k].z);
                accLo[k].w = fmaf(xr[k], wA0.w, accLo[k].w); accLo[k].w = fmaf(xi[k], wB0.w, accLo[k].w);
                accHi[k].x = fmaf(xr[k], wA1.x, accHi[k].x); accHi[k].x = fmaf(xi[k], wB1.x, accHi[k].x);
                accHi[k].y = fmaf(xr[k], wA1.y, accHi[k].y); accHi[k].y = fmaf(xi[k], wB1.y, accHi[k].y);
                accHi[k].z = fmaf(xr[k], wA1.z, accHi[k].z); accHi[k].z = fmaf(xi[k], wB1.z, accHi[k].z);
                accHi[k].w = fmaf(xr[k], wA1.w, accHi[k].w); accHi[k].w = fmaf(xi[k], wB1.w, accHi[k].w);
            }
        }

        __syncwarp();                        // all lanes done reading buf
        if (c < 14) {
            FILL_CHUNK(c + 2, buf);
        } else {
            cp_commit();                     // keep group accounting uniform
        }
    }

    // ---- store: out[b, cout, 4p..4p+3, :] = contiguous 64-float run ----
    #pragma unroll
    for (int k = 0; k < 4; k++) {
        const int b = bslot * 4 + k;
        const size_t off = (((size_t)(b * 2 + cout) * N_) + 4 * (size_t)p) * 16;
        *(float4*)&out[off + oslot * 4]      = accLo[k];
        *(float4*)&out[off + 32 + oslot * 4] = accHi[k];
    }
    #undef FILL_CHUNK
}

extern "C" void kernel_launch(void* const* d_in, const int* in_sizes, int n_in,
                              void* d_out, int out_size)
{
    const float* x    = (const float*)d_in[0];
    const float* Wrr  = (const float*)d_in[1];
    const float* Wri  = (const float*)d_in[2];
    const float* Wir  = (const float*)d_in[3];
    const float* Wii  = (const float*)d_in[4];
    const int*   perm = (const int*)d_in[5];
    float* out = (float*)d_out;

    butterfly_local_v5<<<P_ / 2, 64>>>(x, Wrr, Wri, Wir, Wii, perm, out);
}